// round 11
// baseline (speedup 1.0000x reference)
#include <cuda_runtime.h>
#include <math.h>
#include <stdint.h>

// ---------------------------------------------------------------------------
// FNO2d: B=16, Cin=5, S=128, W=64 ch, M=16 modes, D=4 layers, PAD=9 -> H=137
// Packed fp32 (fma.rn.f32x2) everywhere; mlp1+mlp2+skip fused per pixel;
// invrow+invcol fused through shared memory (phase-1 coverage fixed).
// ---------------------------------------------------------------------------

#define NB 16
#define NC 64
#define NH 137
#define NPIX (137*137)      // 18769
#define NM 16
#define NKX 32
#define ND 4
#define NBC (NB*NC)         // 1024

typedef unsigned long long u64t;

static __device__ __align__(16) float g_x[NBC*NPIX];       // field [bc][x*137+y]
static __device__ __align__(16) float g_a[NBC*NPIX];       // scratch
static __device__ __align__(16) float g_Y[NBC*NH*32];      // col DFT [bc][x][2m+p]
static __device__ __align__(16) float g_Z[512*2*NBC];      // spectrum [kk][p][bc]
static __device__ __align__(16) float g_S[NBC*1024];       // mixed [bo][kx][ky][p]
static __device__ __align__(16) float g_wm[ND*512*2*4096]; // [d][kk][p][i*64+o]
static __device__ __align__(16) float g_Ft[NH*32];         // fwd col [y][2m+p]
static __device__ __align__(16) float g_Gt[NH*64];         // fwd row [x][2kx+p]
static __device__ __align__(16) float g_Et[32*2*NH];       // inv row [kx][2x+p]
static __device__ __align__(16) float g_Tt[NH*32];         // inv col [y][2ky+p]

__device__ __forceinline__ float gelu_f(float v) {
    return 0.5f * v * (1.0f + erff(v * 0.70710678118654752440f));
}

// ---------------- packed fp32 (f32x2) primitives ---------------------------
__device__ __forceinline__ u64t ffma2(u64t a, u64t b, u64t c) {
    u64t d;
    asm("fma.rn.f32x2 %0, %1, %2, %3;" : "=l"(d) : "l"(a), "l"(b), "l"(c));
    return d;
}
__device__ __forceinline__ u64t pack2(float lo, float hi) {
    u64t d;
    asm("mov.b64 %0, {%1, %2};" : "=l"(d) : "f"(lo), "f"(hi));
    return d;
}
__device__ __forceinline__ void unpack2(u64t v, float& lo, float& hi) {
    asm("mov.b64 {%0, %1}, %2;" : "=f"(lo), "=f"(hi) : "l"(v));
}
#define ZERO2 0ULL

// ---------------- twiddle tables (double-precision sincos) -----------------
__global__ void k_tables() {
    int idx = blockIdx.x * blockDim.x + threadIdx.x;
    if (idx >= NKX * NH) return;
    int j = idx / NH, t = idx - j * NH;
    int gk = (j < NM) ? j : (NH - NKX + j);
    const double TWO_PI = 6.283185307179586476925286766559;
    double th = TWO_PI * (double)gk * (double)t / (double)NH;
    double s, c;
    sincos(th, &s, &c);
    g_Gt[t*64 + 2*j]     = (float)c;
    g_Gt[t*64 + 2*j + 1] = (float)(-s);
    g_Et[j*(2*NH) + 2*t]     = (float)c;
    g_Et[j*(2*NH) + 2*t + 1] = (float)(s);
    if (j < NM) {
        g_Ft[t*32 + 2*j]     = (float)c;
        g_Ft[t*32 + 2*j + 1] = (float)(-s);
        double wgt = ((j == 0) ? 1.0 : 2.0) / ((double)NH * (double)NH);
        g_Tt[t*32 + 2*j]     = (float)(wgt * c);
        g_Tt[t*32 + 2*j + 1] = (float)(-wgt * s);
    }
}

// ------------- spectral weight transpose: [d][p][i][o][mx][my] -> wm -------
__global__ void k_wt(const float* __restrict__ sw1, const float* __restrict__ sw2) {
    __shared__ float tile[32][33];
    int d   = blockIdx.z >> 2;
    int p   = (blockIdx.z >> 1) & 1;
    int arr = blockIdx.z & 1;
    const float* src = (arr ? sw2 : sw1) + (size_t)(d*2 + p) * 4096 * 256;
    int mxy = blockIdx.x * 32 + threadIdx.x;
    int io  = blockIdx.y * 32 + threadIdx.y;
    tile[threadIdx.y][threadIdx.x] = src[(size_t)io * 256 + mxy];
    __syncthreads();
    int mxy2 = blockIdx.x * 32 + threadIdx.y;
    int io2  = blockIdx.y * 32 + threadIdx.x;
    g_wm[((size_t)(d*512 + arr*256 + mxy2) * 2 + p) * 4096 + io2] = tile[threadIdx.x][threadIdx.y];
}

// ---------------- embed: concat grids, project 7->64, zero-pad -------------
__global__ __launch_bounds__(160) void k_embed(const float* __restrict__ xin,
                                               const float* __restrict__ pw,
                                               const float* __restrict__ pb) {
    __shared__ float spw[448];
    __shared__ float spb[64];
    int tid = threadIdx.x;
    for (int j = tid; j < 448; j += 160) spw[j] = pw[j];
    if (tid < 64) spb[tid] = pb[tid];
    __syncthreads();
    int b = blockIdx.y, x = blockIdx.x, y = tid;
    if (y >= NH) return;
    bool interior = (x < 128 && y < 128);
    float c[5]; float gx = 0.f, gy = 0.f;
    if (interior) {
        const float* src = xin + ((size_t)(b*5) * 128 + x) * 128 + y;
        #pragma unroll
        for (int i = 0; i < 5; i++) c[i] = src[(size_t)i * 128 * 128];
        const float step = 1.0f / 127.0f;
        gx = x * step; gy = y * step;
    }
    float* dst = g_x + ((size_t)(b*64) * NH + x) * NH + y;
    #pragma unroll 4
    for (int dd = 0; dd < 64; dd++) {
        float s = 0.f;
        if (interior) {
            s = spb[dd];
            #pragma unroll
            for (int i = 0; i < 5; i++) s += c[i] * spw[i*64 + dd];
            s += gx * spw[5*64 + dd] + gy * spw[6*64 + dd];
        }
        dst[(size_t)dd * NPIX] = s;
    }
}

// ------- forward column DFT: 32-row tile, row-pair f32x2 packing -----------
__global__ __launch_bounds__(128) void k_coldft() {
    __shared__ __align__(16) float sx[NH*34];   // [y][xr] pitch 34 (even)
    int bc = blockIdx.y;
    int x0 = blockIdx.x * 32;
    int tid = threadIdx.x;
    const float* xin = g_x + (size_t)bc * NPIX;
    for (int idx = tid; idx < 32*NH; idx += 128) {
        int xr = idx / NH, y = idx - xr*NH;
        float v = (x0 + xr < NH) ? xin[(size_t)(x0+xr)*NH + y] : 0.f;
        sx[y*34 + xr] = v;
    }
    __syncthreads();
    int cg = tid & 15, rg = tid >> 4;     // 16 col-groups x 8 row-groups
    int c0 = cg*2, r0 = rg*4;             // 2 cols x 4 rows (2 pairs)
    u64t a00 = ZERO2, a01 = ZERO2, a10 = ZERO2, a11 = ZERO2;
    #pragma unroll 4
    for (int y = 0; y < NH; y++) {
        float2 f = *(const float2*)&g_Ft[y*32 + c0];   // L1-resident
        u64t fx = pack2(f.x, f.x), fy = pack2(f.y, f.y);
        const u64t* px = (const u64t*)&sx[y*34 + r0];  // even offset -> 8B ok
        u64t p0 = px[0], p1 = px[1];
        a00 = ffma2(p0, fx, a00); a01 = ffma2(p0, fy, a01);
        a10 = ffma2(p1, fx, a10); a11 = ffma2(p1, fy, a11);
    }
    int r = x0 + r0;
    float u0, u1, v0, v1;
    unpack2(a00, u0, u1); unpack2(a01, v0, v1);
    if (r < NH)     { size_t o = ((size_t)bc*NH + r    )*32 + c0; g_Y[o] = u0; g_Y[o+1] = v0; }
    if (r + 1 < NH) { size_t o = ((size_t)bc*NH + r + 1)*32 + c0; g_Y[o] = u1; g_Y[o+1] = v1; }
    unpack2(a10, u0, u1); unpack2(a11, v0, v1);
    if (r + 2 < NH) { size_t o = ((size_t)bc*NH + r + 2)*32 + c0; g_Y[o] = u0; g_Y[o+1] = v0; }
    if (r + 3 < NH) { size_t o = ((size_t)bc*NH + r + 3)*32 + c0; g_Y[o] = u1; g_Y[o+1] = v1; }
}

// ------- forward row DFT over x: C[16ky x 32kx] complex, K=137 -------------
__global__ __launch_bounds__(128) void k_rowdft() {
    __shared__ __align__(16) float ys[NH*36];   // [x][2ky+p] pad 36
    int bc = blockIdx.x;
    int tid = threadIdx.x;
    for (int idx = tid; idx < NH*32; idx += 128) {
        int x = idx >> 5, c = idx & 31;
        ys[x*36 + c] = g_Y[((size_t)bc*NH + x)*32 + c];
    }
    __syncthreads();
    int tx = tid & 31;            // kx
    int ty = tid >> 5;            // ky group of 4
    u64t acc0 = ZERO2, acc1 = ZERO2, acc2 = ZERO2, acc3 = ZERO2;  // (re,im)
    #pragma unroll 2
    for (int x = 0; x < NH; x++) {
        const float4* yp = (const float4*)&ys[x*36 + ty*8];
        float4 yA = yp[0];
        float4 yB = yp[1];
        float gc = g_Gt[x*64 + 2*tx];
        float gs = g_Gt[x*64 + 2*tx + 1];
        u64t gP = pack2(gc, gs);
        u64t gN = pack2(-gs, gc);
        acc0 = ffma2(pack2(yA.x, yA.x), gP, ffma2(pack2(yA.y, yA.y), gN, acc0));
        acc1 = ffma2(pack2(yA.z, yA.z), gP, ffma2(pack2(yA.w, yA.w), gN, acc1));
        acc2 = ffma2(pack2(yB.x, yB.x), gP, ffma2(pack2(yB.y, yB.y), gN, acc2));
        acc3 = ffma2(pack2(yB.z, yB.z), gP, ffma2(pack2(yB.w, yB.w), gN, acc3));
    }
    u64t accs[4] = {acc0, acc1, acc2, acc3};
    #pragma unroll
    for (int j = 0; j < 4; j++) {
        int ky = ty*4 + j;
        size_t base = (size_t)((tx*16 + ky)*2)*NBC + bc;
        float re, im;
        unpack2(accs[j], re, im);
        g_Z[base]       = re;
        g_Z[base + NBC] = im;
    }
}

// --- spectral channel mix: batch-pair f32x2 packing, Z transposed in smem ---
__global__ __launch_bounds__(256) void k_mix(int d) {
    __shared__ __align__(16) float zrt[64*18], zit[64*18];   // [chan][batch] pitch 18
    __shared__ float wr[4096], wi[4096];
    int kk = blockIdx.x;
    int tid = threadIdx.x;
    const float* wb = g_wm + ((size_t)(d*512 + kk) * 2) * 4096;
    for (int idx = tid; idx < 1024; idx += 256) {
        int chan = idx & 63, b = idx >> 6;
        zrt[chan*18 + b] = g_Z[(size_t)(kk*2)*NBC + idx];
        zit[chan*18 + b] = g_Z[(size_t)(kk*2 + 1)*NBC + idx];
    }
    for (int idx = tid; idx < 4096; idx += 256) {
        wr[idx] = wb[idx];
        wi[idx] = wb[4096 + idx];
    }
    __syncthreads();
    int kx = kk >> 4, ky = kk & 15;
    int o = tid & 63, bg = tid >> 6;      // 4 batches (2 pairs) per thread
    u64t accr0 = ZERO2, acci0 = ZERO2, accr1 = ZERO2, acci1 = ZERO2;
    #pragma unroll 2
    for (int i = 0; i < 64; i++) {
        float wrv = wr[i*64 + o], wiv = wi[i*64 + o];
        u64t w_r = pack2(wrv, wrv);
        u64t w_i = pack2(wiv, wiv);
        u64t w_n = pack2(-wiv, -wiv);
        const u64t* zr2 = (const u64t*)&zrt[i*18 + bg*4];   // even offsets
        const u64t* zi2 = (const u64t*)&zit[i*18 + bg*4];
        u64t a0 = zr2[0], a1 = zr2[1];
        u64t b0 = zi2[0], b1 = zi2[1];
        accr0 = ffma2(a0, w_r, ffma2(b0, w_n, accr0));
        acci0 = ffma2(a0, w_i, ffma2(b0, w_r, acci0));
        accr1 = ffma2(a1, w_r, ffma2(b1, w_n, accr1));
        acci1 = ffma2(a1, w_i, ffma2(b1, w_r, acci1));
    }
    float r0, r1, r2, r3, i0, i1, i2, i3;
    unpack2(accr0, r0, r1); unpack2(acci0, i0, i1);
    unpack2(accr1, r2, r3); unpack2(acci1, i2, i3);
    int bbase = bg*4;
    size_t tail = (size_t)kx*32 + ky*2;
    *(u64t*)&g_S[(size_t)((bbase+0)*64 + o)*1024 + tail] = pack2(r0, i0);
    *(u64t*)&g_S[(size_t)((bbase+1)*64 + o)*1024 + tail] = pack2(r1, i1);
    *(u64t*)&g_S[(size_t)((bbase+2)*64 + o)*1024 + tail] = pack2(r2, i2);
    *(u64t*)&g_S[(size_t)((bbase+3)*64 + o)*1024 + tail] = pack2(r3, i3);
}

// ------- fused inverse 2D: invrow (smem) + invcol, one block per bo --------
__global__ __launch_bounds__(256) void k_inv2d() {
    __shared__ float ss[1024];                   // [kx][2ky+p]
    __shared__ __align__(16) float su[NH*34];    // [x][2ky+p] pitch 34
    __shared__ __align__(16) float ts[NH*36];    // [y][2ky+p] pitch 36
    int bo = blockIdx.x, tid = threadIdx.x;
    for (int idx = tid; idx < 1024; idx += 256) ss[idx] = g_S[(size_t)bo*1024 + idx];
    for (int idx = tid; idx < NH*32; idx += 256) {
        int y = idx >> 5, c = idx & 31;
        ts[y*36 + c] = g_Tt[idx];
    }
    __syncthreads();
    // phase 1: inverse row transform -> su (2 slots per x, strided coverage)
    for (int t = tid; t < 2*NH; t += 256) {
        int x = t >> 1;
        int ky0 = (t & 1) * 8;
        u64t acc[8];
        #pragma unroll
        for (int j = 0; j < 8; j++) acc[j] = ZERO2;
        for (int k = 0; k < 32; k++) {
            float2 e = *(const float2*)&g_Et[k*(2*NH) + 2*x];    // L1-resident
            u64t eP = pack2(e.x, e.y);
            u64t eN = pack2(-e.y, e.x);
            #pragma unroll
            for (int j = 0; j < 8; j++) {
                float2 s = *(const float2*)&ss[k*32 + 2*(ky0 + j)];   // broadcast
                acc[j] = ffma2(pack2(s.x, s.x), eP, ffma2(pack2(s.y, s.y), eN, acc[j]));
            }
        }
        u64t* up = (u64t*)&su[x*34 + 2*ky0];
        #pragma unroll
        for (int j = 0; j < 8; j++) up[j] = acc[j];   // (re,im) pairs
    }
    __syncthreads();
    // phase 2: inverse column transform, lane = y, coalesced stores
    int ly = tid & 31, xg = tid >> 5;
    float* dst = g_a + (size_t)bo*NPIX;
    for (int x = xg; x < NH; x += 8) {
        u64t u2[16];
        const u64t* up = (const u64t*)&su[x*34];
        #pragma unroll
        for (int k = 0; k < 16; k++) u2[k] = up[k];   // broadcast
        for (int y = ly; y < NH; y += 32) {
            const ulonglong2* t2 = (const ulonglong2*)&ts[y*36];
            u64t acc2 = ZERO2;
            #pragma unroll
            for (int k2 = 0; k2 < 8; k2++) {
                ulonglong2 t = t2[k2];
                acc2 = ffma2(u2[2*k2], t.x, acc2);
                acc2 = ffma2(u2[2*k2+1], t.y, acc2);
            }
            float lo, hi;
            unpack2(acc2, lo, hi);
            dst[(size_t)x*NH + y] = lo + hi;
        }
    }
}

// ---- fused mlp: x = gelu( W2·gelu(W1·a + b1) + b2 + Ww·x + wb ), per pixel ----
__global__ __launch_bounds__(128)
void k_mlpf(const float* __restrict__ m1w, const float* __restrict__ m1b,
            const float* __restrict__ m2w, const float* __restrict__ m2b,
            const float* __restrict__ wwp, const float* __restrict__ wbp, int d) {
    __shared__ __align__(16) float s1[4096];   // W1 [m][i] (natural row-major)
    __shared__ __align__(16) float s2[4096];   // W2T [m][o]
    __shared__ __align__(16) float s3[4096];   // W3T [i][o]
    __shared__ float sb1[64], sb2[64];
    int tid = threadIdx.x;
    const float* w1s = m1w + (size_t)d*4096;
    const float* w2s = m2w + (size_t)d*4096;
    const float* w3s = wwp + (size_t)d*4096;
    for (int j = tid; j < 4096; j += 128) {
        s1[j] = w1s[j];
        int o = j & 63, i = j >> 6;
        s2[j] = w2s[o*64 + i];
        s3[j] = w3s[o*64 + i];
    }
    if (tid < 64) {
        sb1[tid] = m1b[d*64 + tid];
        sb2[tid] = m2b[d*64 + tid] + wbp[d*64 + tid];
    }
    __syncthreads();
    int b = blockIdx.y;
    int p = blockIdx.x*128 + tid;
    if (p >= NPIX) return;
    const float* asrc = g_a + (size_t)b*64*NPIX + p;
    float* xsrc = g_x + (size_t)b*64*NPIX + p;

    u64t a2[32];            // packed input channel pairs
    u64t acc[32];           // packed output accumulators (skip + mlp2)
    #pragma unroll
    for (int j = 0; j < 32; j++) acc[j] = pack2(sb2[2*j], sb2[2*j+1]);

    // pass 1: load a, accumulate skip path Ww·x
    for (int i = 0; i < 64; i += 2) {
        float a0 = asrc[(size_t)i*NPIX];
        float a1 = asrc[(size_t)(i+1)*NPIX];
        a2[i>>1] = pack2(a0, a1);
        float x0 = xsrc[(size_t)i*NPIX];
        float x1 = xsrc[(size_t)(i+1)*NPIX];
        u64t xv0 = pack2(x0, x0), xv1 = pack2(x1, x1);
        const ulonglong2* w3a = (const ulonglong2*)(s3 + i*64);
        const ulonglong2* w3b = (const ulonglong2*)(s3 + (i+1)*64);
        #pragma unroll
        for (int q = 0; q < 16; q++) {
            ulonglong2 wa = w3a[q], wb = w3b[q];
            acc[2*q]   = ffma2(wa.x, xv0, ffma2(wb.x, xv1, acc[2*q]));
            acc[2*q+1] = ffma2(wa.y, xv0, ffma2(wb.y, xv1, acc[2*q+1]));
        }
    }
    // pass 2: per intermediate channel pair: h = gelu(W1·a + b1), acc += W2T·h
    for (int m = 0; m < 64; m += 2) {
        u64t d0 = ZERO2, d1 = ZERO2;
        const ulonglong2* w1a = (const ulonglong2*)(s1 + m*64);
        const ulonglong2* w1b = (const ulonglong2*)(s1 + (m+1)*64);
        #pragma unroll
        for (int q = 0; q < 16; q++) {
            ulonglong2 wa = w1a[q], wb = w1b[q];
            d0 = ffma2(wa.x, a2[2*q], d0); d0 = ffma2(wa.y, a2[2*q+1], d0);
            d1 = ffma2(wb.x, a2[2*q], d1); d1 = ffma2(wb.y, a2[2*q+1], d1);
        }
        float h0lo, h0hi, h1lo, h1hi;
        unpack2(d0, h0lo, h0hi); unpack2(d1, h1lo, h1hi);
        float h0 = gelu_f(sb1[m]   + (h0lo + h0hi));
        float h1 = gelu_f(sb1[m+1] + (h1lo + h1hi));
        u64t hv0 = pack2(h0, h0), hv1 = pack2(h1, h1);
        const ulonglong2* w2a = (const ulonglong2*)(s2 + m*64);
        const ulonglong2* w2b = (const ulonglong2*)(s2 + (m+1)*64);
        #pragma unroll
        for (int q = 0; q < 16; q++) {
            ulonglong2 wa = w2a[q], wb = w2b[q];
            acc[2*q]   = ffma2(wa.x, hv0, ffma2(wb.x, hv1, acc[2*q]));
            acc[2*q+1] = ffma2(wa.y, hv0, ffma2(wb.y, hv1, acc[2*q+1]));
        }
    }
    #pragma unroll
    for (int j = 0; j < 32; j++) {
        float lo, hi;
        unpack2(acc[j], lo, hi);
        xsrc[(size_t)(2*j)*NPIX]   = gelu_f(lo);
        xsrc[(size_t)(2*j+1)*NPIX] = gelu_f(hi);
    }
}

// -------- head: crop + q1(64->256) + gelu + q2(256->1), two m-halves -------
__global__ __launch_bounds__(256) void k_head(const float* __restrict__ q1w,
                                              const float* __restrict__ q1b,
                                              const float* __restrict__ q2w,
                                              const float* __restrict__ q2b,
                                              float* __restrict__ out) {
    __shared__ __align__(16) float sw[8192];
    __shared__ float sb1[128], s2[128];
    int tid = threadIdx.x, b = blockIdx.y;
    int idx = blockIdx.x*256 + tid;
    int x = idx >> 7, y = idx & 127;
    const float* src = g_x + (size_t)b*64*NPIX + x*NH + y;
    u64t v2[32];
    #pragma unroll
    for (int i = 0; i < 32; i++)
        v2[i] = pack2(src[(size_t)(2*i)*NPIX], src[(size_t)(2*i+1)*NPIX]);
    float o = q2b[0];
    for (int half = 0; half < 2; half++) {
        __syncthreads();
        for (int j = tid; j < 8192; j += 256) sw[j] = q1w[half*8192 + j];
        if (tid < 128) { sb1[tid] = q1b[half*128 + tid]; s2[tid] = q2w[half*128 + tid]; }
        __syncthreads();
        for (int m = 0; m < 128; m++) {
            u64t h2a = ZERO2, h2b = ZERO2;
            const ulonglong2* w2 = (const ulonglong2*)(sw + m*64);
            #pragma unroll
            for (int q = 0; q < 16; q++) {
                ulonglong2 ww = w2[q];
                h2a = ffma2(ww.x, v2[2*q],   h2a);
                h2b = ffma2(ww.y, v2[2*q+1], h2b);
            }
            float l0, h0, l1, h1;
            unpack2(h2a, l0, h0);
            unpack2(h2b, l1, h1);
            o += s2[m] * gelu_f(sb1[m] + (l0 + h0) + (l1 + h1));
        }
    }
    out[(size_t)b*16384 + idx] = o;
}

// ---------------------------------------------------------------------------
extern "C" void kernel_launch(void* const* d_in, const int* in_sizes, int n_in,
                              void* d_out, int out_size) {
    const float* x   = (const float*)d_in[0];
    const float* p_w = (const float*)d_in[1];
    const float* p_b = (const float*)d_in[2];
    const float* sw1 = (const float*)d_in[3];
    const float* sw2 = (const float*)d_in[4];
    const float* m1w = (const float*)d_in[5];
    const float* m1b = (const float*)d_in[6];
    const float* m2w = (const float*)d_in[7];
    const float* m2b = (const float*)d_in[8];
    const float* wwp = (const float*)d_in[9];
    const float* wbp = (const float*)d_in[10];
    const float* q1w = (const float*)d_in[11];
    const float* q1b = (const float*)d_in[12];
    const float* q2w = (const float*)d_in[13];
    const float* q2b = (const float*)d_in[14];
    float* out = (float*)d_out;

    k_tables<<<18, 256>>>();
    k_wt<<<dim3(8, 128, 16), dim3(32, 32)>>>(sw1, sw2);
    k_embed<<<dim3(137, 16), 160>>>(x, p_w, p_b);

    const int mlpfblocks = (NPIX + 127) / 128;   // 147
    for (int d = 0; d < ND; d++) {
        k_coldft<<<dim3(5, NBC), 128>>>();
        k_rowdft<<<NBC, 128>>>();
        k_mix<<<512, 256>>>(d);
        k_inv2d<<<NBC, 256>>>();
        k_mlpf<<<dim3(mlpfblocks, NB), 128>>>(m1w, m1b, m2w, m2b, wwp, wbp, d);
    }

    k_head<<<dim3(64, NB), 256>>>(q1w, q1b, q2w, q2b, out);
}

// round 12
// speedup vs baseline: 1.0004x; 1.0004x over previous
#include <cuda_runtime.h>
#include <math.h>
#include <stdint.h>

// ---------------------------------------------------------------------------
// FNO2d: B=16, Cin=5, S=128, W=64 ch, M=16 modes, D=4 layers, PAD=9 -> H=137
// Packed fp32 (fma.rn.f32x2) everywhere; split mlp kernels (fusion regressed);
// coldft 4x4 register tile with LDS.128/LDG.128 operands.
// ---------------------------------------------------------------------------

#define NB 16
#define NC 64
#define NH 137
#define NPIX (137*137)      // 18769
#define NM 16
#define NKX 32
#define ND 4
#define NBC (NB*NC)         // 1024

typedef unsigned long long u64t;

static __device__ __align__(16) float g_x[NBC*NPIX];       // field [bc][x*137+y]
static __device__ __align__(16) float g_a[NBC*NPIX];       // scratch
static __device__ __align__(16) float g_Y[NBC*NH*32];      // col DFT [bc][x][2m+p]
static __device__ __align__(16) float g_Z[512*2*NBC];      // spectrum [kk][p][bc]
static __device__ __align__(16) float g_S[NBC*1024];       // mixed [bo][kx][ky][p]
static __device__ __align__(16) float g_wm[ND*512*2*4096]; // [d][kk][p][i*64+o]
static __device__ __align__(16) float g_Ft[NH*32];         // fwd col [y][2m+p]
static __device__ __align__(16) float g_Gt[NH*64];         // fwd row [x][2kx+p]
static __device__ __align__(16) float g_Et[32*2*NH];       // inv row [kx][2x+p]
static __device__ __align__(16) float g_Tt[NH*32];         // inv col [y][2ky+p]

__device__ __forceinline__ float gelu_f(float v) {
    return 0.5f * v * (1.0f + erff(v * 0.70710678118654752440f));
}

// ---------------- packed fp32 (f32x2) primitives ---------------------------
__device__ __forceinline__ u64t ffma2(u64t a, u64t b, u64t c) {
    u64t d;
    asm("fma.rn.f32x2 %0, %1, %2, %3;" : "=l"(d) : "l"(a), "l"(b), "l"(c));
    return d;
}
__device__ __forceinline__ u64t pack2(float lo, float hi) {
    u64t d;
    asm("mov.b64 %0, {%1, %2};" : "=l"(d) : "f"(lo), "f"(hi));
    return d;
}
__device__ __forceinline__ void unpack2(u64t v, float& lo, float& hi) {
    asm("mov.b64 {%0, %1}, %2;" : "=f"(lo), "=f"(hi) : "l"(v));
}
#define ZERO2 0ULL

// ---------------- twiddle tables (double-precision sincos) -----------------
__global__ void k_tables() {
    int idx = blockIdx.x * blockDim.x + threadIdx.x;
    if (idx >= NKX * NH) return;
    int j = idx / NH, t = idx - j * NH;
    int gk = (j < NM) ? j : (NH - NKX + j);
    const double TWO_PI = 6.283185307179586476925286766559;
    double th = TWO_PI * (double)gk * (double)t / (double)NH;
    double s, c;
    sincos(th, &s, &c);
    g_Gt[t*64 + 2*j]     = (float)c;
    g_Gt[t*64 + 2*j + 1] = (float)(-s);
    g_Et[j*(2*NH) + 2*t]     = (float)c;
    g_Et[j*(2*NH) + 2*t + 1] = (float)(s);
    if (j < NM) {
        g_Ft[t*32 + 2*j]     = (float)c;
        g_Ft[t*32 + 2*j + 1] = (float)(-s);
        double wgt = ((j == 0) ? 1.0 : 2.0) / ((double)NH * (double)NH);
        g_Tt[t*32 + 2*j]     = (float)(wgt * c);
        g_Tt[t*32 + 2*j + 1] = (float)(-wgt * s);
    }
}

// ------------- spectral weight transpose: [d][p][i][o][mx][my] -> wm -------
__global__ void k_wt(const float* __restrict__ sw1, const float* __restrict__ sw2) {
    __shared__ float tile[32][33];
    int d   = blockIdx.z >> 2;
    int p   = (blockIdx.z >> 1) & 1;
    int arr = blockIdx.z & 1;
    const float* src = (arr ? sw2 : sw1) + (size_t)(d*2 + p) * 4096 * 256;
    int mxy = blockIdx.x * 32 + threadIdx.x;
    int io  = blockIdx.y * 32 + threadIdx.y;
    tile[threadIdx.y][threadIdx.x] = src[(size_t)io * 256 + mxy];
    __syncthreads();
    int mxy2 = blockIdx.x * 32 + threadIdx.y;
    int io2  = blockIdx.y * 32 + threadIdx.x;
    g_wm[((size_t)(d*512 + arr*256 + mxy2) * 2 + p) * 4096 + io2] = tile[threadIdx.x][threadIdx.y];
}

// ---------------- embed: concat grids, project 7->64, zero-pad -------------
__global__ __launch_bounds__(160) void k_embed(const float* __restrict__ xin,
                                               const float* __restrict__ pw,
                                               const float* __restrict__ pb) {
    __shared__ float spw[448];
    __shared__ float spb[64];
    int tid = threadIdx.x;
    for (int j = tid; j < 448; j += 160) spw[j] = pw[j];
    if (tid < 64) spb[tid] = pb[tid];
    __syncthreads();
    int b = blockIdx.y, x = blockIdx.x, y = tid;
    if (y >= NH) return;
    bool interior = (x < 128 && y < 128);
    float c[5]; float gx = 0.f, gy = 0.f;
    if (interior) {
        const float* src = xin + ((size_t)(b*5) * 128 + x) * 128 + y;
        #pragma unroll
        for (int i = 0; i < 5; i++) c[i] = src[(size_t)i * 128 * 128];
        const float step = 1.0f / 127.0f;
        gx = x * step; gy = y * step;
    }
    float* dst = g_x + ((size_t)(b*64) * NH + x) * NH + y;
    #pragma unroll 4
    for (int dd = 0; dd < 64; dd++) {
        float s = 0.f;
        if (interior) {
            s = spb[dd];
            #pragma unroll
            for (int i = 0; i < 5; i++) s += c[i] * spw[i*64 + dd];
            s += gx * spw[5*64 + dd] + gy * spw[6*64 + dd];
        }
        dst[(size_t)dd * NPIX] = s;
    }
}

// ------- forward column DFT: 64-row tile, 4x4 register blocks --------------
__global__ __launch_bounds__(128) void k_coldft() {
    __shared__ __align__(16) float sx[NH*68];   // [y][xr] pitch 68 (mult of 4)
    int bc = blockIdx.y;
    int x0 = blockIdx.x * 64;
    int tid = threadIdx.x;
    const float* xin = g_x + (size_t)bc * NPIX;
    for (int idx = tid; idx < 64*NH; idx += 128) {
        int xr = idx / NH, y = idx - xr*NH;
        float v = (x0 + xr < NH) ? xin[(size_t)(x0+xr)*NH + y] : 0.f;
        sx[y*68 + xr] = v;
    }
    __syncthreads();
    int cg = tid & 7, rg = tid >> 3;      // 8 col-groups x 16 row-groups
    int c0 = cg*4, r0 = rg*4;             // 4 cols (2 pairs) x 4 rows
    u64t acc[4][2];
    #pragma unroll
    for (int jr = 0; jr < 4; jr++) { acc[jr][0] = ZERO2; acc[jr][1] = ZERO2; }
    #pragma unroll 2
    for (int y = 0; y < NH; y++) {
        ulonglong2 f = *(const ulonglong2*)&g_Ft[y*32 + c0];    // 4 twiddles, L1
        ulonglong2 p = *(const ulonglong2*)&sx[y*68 + r0];      // 4 rows, LDS.128
        float v0, v1, v2, v3;
        unpack2(p.x, v0, v1); unpack2(p.y, v2, v3);
        u64t s0 = pack2(v0, v0), s1 = pack2(v1, v1);
        u64t s2 = pack2(v2, v2), s3 = pack2(v3, v3);
        acc[0][0] = ffma2(s0, f.x, acc[0][0]); acc[0][1] = ffma2(s0, f.y, acc[0][1]);
        acc[1][0] = ffma2(s1, f.x, acc[1][0]); acc[1][1] = ffma2(s1, f.y, acc[1][1]);
        acc[2][0] = ffma2(s2, f.x, acc[2][0]); acc[2][1] = ffma2(s2, f.y, acc[2][1]);
        acc[3][0] = ffma2(s3, f.x, acc[3][0]); acc[3][1] = ffma2(s3, f.y, acc[3][1]);
    }
    #pragma unroll
    for (int jr = 0; jr < 4; jr++) {
        int r = x0 + r0 + jr;
        if (r < NH) {
            float4 o;
            unpack2(acc[jr][0], o.x, o.y);
            unpack2(acc[jr][1], o.z, o.w);
            *(float4*)&g_Y[((size_t)bc*NH + r)*32 + c0] = o;
        }
    }
}

// ------- forward row DFT over x: C[16ky x 32kx] complex, K=137 -------------
__global__ __launch_bounds__(128) void k_rowdft() {
    __shared__ __align__(16) float ys[NH*36];   // [x][2ky+p] pad 36
    int bc = blockIdx.x;
    int tid = threadIdx.x;
    for (int idx = tid; idx < NH*32; idx += 128) {
        int x = idx >> 5, c = idx & 31;
        ys[x*36 + c] = g_Y[((size_t)bc*NH + x)*32 + c];
    }
    __syncthreads();
    int tx = tid & 31;            // kx
    int ty = tid >> 5;            // ky group of 4
    u64t acc0 = ZERO2, acc1 = ZERO2, acc2 = ZERO2, acc3 = ZERO2;  // (re,im)
    #pragma unroll 2
    for (int x = 0; x < NH; x++) {
        const float4* yp = (const float4*)&ys[x*36 + ty*8];
        float4 yA = yp[0];
        float4 yB = yp[1];
        float gc = g_Gt[x*64 + 2*tx];
        float gs = g_Gt[x*64 + 2*tx + 1];
        u64t gP = pack2(gc, gs);
        u64t gN = pack2(-gs, gc);
        acc0 = ffma2(pack2(yA.x, yA.x), gP, ffma2(pack2(yA.y, yA.y), gN, acc0));
        acc1 = ffma2(pack2(yA.z, yA.z), gP, ffma2(pack2(yA.w, yA.w), gN, acc1));
        acc2 = ffma2(pack2(yB.x, yB.x), gP, ffma2(pack2(yB.y, yB.y), gN, acc2));
        acc3 = ffma2(pack2(yB.z, yB.z), gP, ffma2(pack2(yB.w, yB.w), gN, acc3));
    }
    u64t accs[4] = {acc0, acc1, acc2, acc3};
    #pragma unroll
    for (int j = 0; j < 4; j++) {
        int ky = ty*4 + j;
        size_t base = (size_t)((tx*16 + ky)*2)*NBC + bc;
        float re, im;
        unpack2(accs[j], re, im);
        g_Z[base]       = re;
        g_Z[base + NBC] = im;
    }
}

// --- spectral channel mix: batch-pair f32x2 packing, Z transposed in smem ---
__global__ __launch_bounds__(256) void k_mix(int d) {
    __shared__ __align__(16) float zrt[64*18], zit[64*18];   // [chan][batch] pitch 18
    __shared__ float wr[4096], wi[4096];
    int kk = blockIdx.x;
    int tid = threadIdx.x;
    const float* wb = g_wm + ((size_t)(d*512 + kk) * 2) * 4096;
    for (int idx = tid; idx < 1024; idx += 256) {
        int chan = idx & 63, b = idx >> 6;
        zrt[chan*18 + b] = g_Z[(size_t)(kk*2)*NBC + idx];
        zit[chan*18 + b] = g_Z[(size_t)(kk*2 + 1)*NBC + idx];
    }
    for (int idx = tid; idx < 4096; idx += 256) {
        wr[idx] = wb[idx];
        wi[idx] = wb[4096 + idx];
    }
    __syncthreads();
    int kx = kk >> 4, ky = kk & 15;
    int o = tid & 63, bg = tid >> 6;      // 4 batches (2 pairs) per thread
    u64t accr0 = ZERO2, acci0 = ZERO2, accr1 = ZERO2, acci1 = ZERO2;
    #pragma unroll 2
    for (int i = 0; i < 64; i++) {
        float wrv = wr[i*64 + o], wiv = wi[i*64 + o];
        u64t w_r = pack2(wrv, wrv);
        u64t w_i = pack2(wiv, wiv);
        u64t w_n = pack2(-wiv, -wiv);
        const u64t* zr2 = (const u64t*)&zrt[i*18 + bg*4];   // even offsets
        const u64t* zi2 = (const u64t*)&zit[i*18 + bg*4];
        u64t a0 = zr2[0], a1 = zr2[1];
        u64t b0 = zi2[0], b1 = zi2[1];
        accr0 = ffma2(a0, w_r, ffma2(b0, w_n, accr0));
        acci0 = ffma2(a0, w_i, ffma2(b0, w_r, acci0));
        accr1 = ffma2(a1, w_r, ffma2(b1, w_n, accr1));
        acci1 = ffma2(a1, w_i, ffma2(b1, w_r, acci1));
    }
    float r0, r1, r2, r3, i0, i1, i2, i3;
    unpack2(accr0, r0, r1); unpack2(acci0, i0, i1);
    unpack2(accr1, r2, r3); unpack2(acci1, i2, i3);
    int bbase = bg*4;
    size_t tail = (size_t)kx*32 + ky*2;
    *(u64t*)&g_S[(size_t)((bbase+0)*64 + o)*1024 + tail] = pack2(r0, i0);
    *(u64t*)&g_S[(size_t)((bbase+1)*64 + o)*1024 + tail] = pack2(r1, i1);
    *(u64t*)&g_S[(size_t)((bbase+2)*64 + o)*1024 + tail] = pack2(r2, i2);
    *(u64t*)&g_S[(size_t)((bbase+3)*64 + o)*1024 + tail] = pack2(r3, i3);
}

// ------- fused inverse 2D: invrow (smem) + invcol, one block per bo --------
__global__ __launch_bounds__(256) void k_inv2d() {
    __shared__ float ss[1024];                   // [kx][2ky+p]
    __shared__ __align__(16) float su[NH*34];    // [x][2ky+p] pitch 34
    __shared__ __align__(16) float ts[NH*36];    // [y][2ky+p] pitch 36
    int bo = blockIdx.x, tid = threadIdx.x;
    for (int idx = tid; idx < 1024; idx += 256) ss[idx] = g_S[(size_t)bo*1024 + idx];
    for (int idx = tid; idx < NH*32; idx += 256) {
        int y = idx >> 5, c = idx & 31;
        ts[y*36 + c] = g_Tt[idx];
    }
    __syncthreads();
    // phase 1: inverse row transform -> su (2 slots per x, strided coverage)
    for (int t = tid; t < 2*NH; t += 256) {
        int x = t >> 1;
        int ky0 = (t & 1) * 8;
        u64t acc[8];
        #pragma unroll
        for (int j = 0; j < 8; j++) acc[j] = ZERO2;
        for (int k = 0; k < 32; k++) {
            float2 e = *(const float2*)&g_Et[k*(2*NH) + 2*x];    // L1-resident
            u64t eP = pack2(e.x, e.y);
            u64t eN = pack2(-e.y, e.x);
            #pragma unroll
            for (int j = 0; j < 8; j++) {
                float2 s = *(const float2*)&ss[k*32 + 2*(ky0 + j)];   // broadcast
                acc[j] = ffma2(pack2(s.x, s.x), eP, ffma2(pack2(s.y, s.y), eN, acc[j]));
            }
        }
        u64t* up = (u64t*)&su[x*34 + 2*ky0];
        #pragma unroll
        for (int j = 0; j < 8; j++) up[j] = acc[j];   // (re,im) pairs
    }
    __syncthreads();
    // phase 2: inverse column transform, lane = y, coalesced stores
    int ly = tid & 31, xg = tid >> 5;
    float* dst = g_a + (size_t)bo*NPIX;
    for (int x = xg; x < NH; x += 8) {
        u64t u2[16];
        const u64t* up = (const u64t*)&su[x*34];
        #pragma unroll
        for (int k = 0; k < 16; k++) u2[k] = up[k];   // broadcast
        for (int y = ly; y < NH; y += 32) {
            const ulonglong2* t2 = (const ulonglong2*)&ts[y*36];
            u64t acc2 = ZERO2;
            #pragma unroll
            for (int k2 = 0; k2 < 8; k2++) {
                ulonglong2 t = t2[k2];
                acc2 = ffma2(u2[2*k2], t.x, acc2);
                acc2 = ffma2(u2[2*k2+1], t.y, acc2);
            }
            float lo, hi;
            unpack2(acc2, lo, hi);
            dst[(size_t)x*NH + y] = lo + hi;
        }
    }
}

// ---------------- conv1x1 (mlp1) + exact gelu, in-place on g_a -------------
__global__ __launch_bounds__(256) void k_mlp1(const float* __restrict__ w,
                                              const float* __restrict__ bias, int d) {
    __shared__ __align__(16) float swT[4096];   // [i*64+o]
    __shared__ float sb[64];
    int tid = threadIdx.x;
    const float* wsrc = w + (size_t)d*4096;     // (o,i)
    for (int j = tid; j < 4096; j += 256) swT[j] = wsrc[(j & 63)*64 + (j >> 6)];
    if (tid < 64) sb[tid] = bias[d*64 + tid];
    __syncthreads();
    int b = blockIdx.y;
    int p = blockIdx.x*256 + tid;
    if (p >= NPIX) return;
    u64t acc2[32];
    #pragma unroll
    for (int j = 0; j < 32; j++) acc2[j] = pack2(sb[2*j], sb[2*j+1]);
    float* base = g_a + (size_t)b*64*NPIX + p;
    float a = base[0];
    for (int i = 0; i < 64; i++) {
        float an = (i < 63) ? base[(size_t)(i+1)*NPIX] : 0.0f;
        u64t av = pack2(a, a);
        const ulonglong2* w2 = (const ulonglong2*)(swT + i*64);
        #pragma unroll
        for (int q = 0; q < 16; q++) {
            ulonglong2 ww = w2[q];
            acc2[2*q]   = ffma2(ww.x, av, acc2[2*q]);
            acc2[2*q+1] = ffma2(ww.y, av, acc2[2*q+1]);
        }
        a = an;
    }
    #pragma unroll
    for (int j = 0; j < 32; j++) {
        float lo, hi;
        unpack2(acc2[j], lo, hi);
        base[(size_t)(2*j)*NPIX]   = gelu_f(lo);
        base[(size_t)(2*j+1)*NPIX] = gelu_f(hi);
    }
}

// -------- fused conv1x1 (mlp2) + skip conv (ww) + gelu, writes g_x ---------
__global__ __launch_bounds__(256) void k_mlp2(const float* __restrict__ w2p,
                                              const float* __restrict__ b2,
                                              const float* __restrict__ wwp,
                                              const float* __restrict__ wbp, int d) {
    __shared__ __align__(16) float s2[4096];
    __shared__ __align__(16) float s3[4096];
    __shared__ float sb[64];
    int tid = threadIdx.x;
    const float* w2s = w2p + (size_t)d*4096;
    const float* w3s = wwp + (size_t)d*4096;
    for (int j = tid; j < 4096; j += 256) {
        int o = j & 63, i = j >> 6;
        s2[j] = w2s[o*64 + i];
        s3[j] = w3s[o*64 + i];
    }
    if (tid < 64) sb[tid] = b2[d*64 + tid] + wbp[d*64 + tid];
    __syncthreads();
    int b = blockIdx.y;
    int p = blockIdx.x*256 + tid;
    if (p >= NPIX) return;
    u64t acc2[32];
    #pragma unroll
    for (int j = 0; j < 32; j++) acc2[j] = pack2(sb[2*j], sb[2*j+1]);
    const float* asrc = g_a + (size_t)b*64*NPIX + p;
    float* xsrc = g_x + (size_t)b*64*NPIX + p;
    float av = asrc[0], xv = xsrc[0];
    for (int i = 0; i < 64; i++) {
        float an = (i < 63) ? asrc[(size_t)(i+1)*NPIX] : 0.0f;
        float xn = (i < 63) ? xsrc[(size_t)(i+1)*NPIX] : 0.0f;
        u64t av2 = pack2(av, av);
        u64t xv2 = pack2(xv, xv);
        const ulonglong2* wa = (const ulonglong2*)(s2 + i*64);
        const ulonglong2* wb4 = (const ulonglong2*)(s3 + i*64);
        #pragma unroll
        for (int q = 0; q < 16; q++) {
            ulonglong2 wwa = wa[q];
            ulonglong2 wwb = wb4[q];
            acc2[2*q]   = ffma2(wwa.x, av2, ffma2(wwb.x, xv2, acc2[2*q]));
            acc2[2*q+1] = ffma2(wwa.y, av2, ffma2(wwb.y, xv2, acc2[2*q+1]));
        }
        av = an; xv = xn;
    }
    #pragma unroll
    for (int j = 0; j < 32; j++) {
        float lo, hi;
        unpack2(acc2[j], lo, hi);
        xsrc[(size_t)(2*j)*NPIX]   = gelu_f(lo);
        xsrc[(size_t)(2*j+1)*NPIX] = gelu_f(hi);
    }
}

// -------- head: crop + q1(64->256) + gelu + q2(256->1), two m-halves -------
__global__ __launch_bounds__(256) void k_head(const float* __restrict__ q1w,
                                              const float* __restrict__ q1b,
                                              const float* __restrict__ q2w,
                                              const float* __restrict__ q2b,
                                              float* __restrict__ out) {
    __shared__ __align__(16) float sw[8192];
    __shared__ float sb1[128], s2[128];
    int tid = threadIdx.x, b = blockIdx.y;
    int idx = blockIdx.x*256 + tid;
    int x = idx >> 7, y = idx & 127;
    const float* src = g_x + (size_t)b*64*NPIX + x*NH + y;
    u64t v2[32];
    #pragma unroll
    for (int i = 0; i < 32; i++)
        v2[i] = pack2(src[(size_t)(2*i)*NPIX], src[(size_t)(2*i+1)*NPIX]);
    float o = q2b[0];
    for (int half = 0; half < 2; half++) {
        __syncthreads();
        for (int j = tid; j < 8192; j += 256) sw[j] = q1w[half*8192 + j];
        if (tid < 128) { sb1[tid] = q1b[half*128 + tid]; s2[tid] = q2w[half*128 + tid]; }
        __syncthreads();
        for (int m = 0; m < 128; m++) {
            u64t h2a = ZERO2, h2b = ZERO2;
            const ulonglong2* w2 = (const ulonglong2*)(sw + m*64);
            #pragma unroll
            for (int q = 0; q < 16; q++) {
                ulonglong2 ww = w2[q];
                h2a = ffma2(ww.x, v2[2*q],   h2a);
                h2b = ffma2(ww.y, v2[2*q+1], h2b);
            }
            float l0, h0, l1, h1;
            unpack2(h2a, l0, h0);
            unpack2(h2b, l1, h1);
            o += s2[m] * gelu_f(sb1[m] + (l0 + h0) + (l1 + h1));
        }
    }
    out[(size_t)b*16384 + idx] = o;
}

// ---------------------------------------------------------------------------
extern "C" void kernel_launch(void* const* d_in, const int* in_sizes, int n_in,
                              void* d_out, int out_size) {
    const float* x   = (const float*)d_in[0];
    const float* p_w = (const float*)d_in[1];
    const float* p_b = (const float*)d_in[2];
    const float* sw1 = (const float*)d_in[3];
    const float* sw2 = (const float*)d_in[4];
    const float* m1w = (const float*)d_in[5];
    const float* m1b = (const float*)d_in[6];
    const float* m2w = (const float*)d_in[7];
    const float* m2b = (const float*)d_in[8];
    const float* wwp = (const float*)d_in[9];
    const float* wbp = (const float*)d_in[10];
    const float* q1w = (const float*)d_in[11];
    const float* q1b = (const float*)d_in[12];
    const float* q2w = (const float*)d_in[13];
    const float* q2b = (const float*)d_in[14];
    float* out = (float*)d_out;

    k_tables<<<18, 256>>>();
    k_wt<<<dim3(8, 128, 16), dim3(32, 32)>>>(sw1, sw2);
    k_embed<<<dim3(137, 16), 160>>>(x, p_w, p_b);

    const int mlpblocks = (NPIX + 255) / 256;
    for (int d = 0; d < ND; d++) {
        k_coldft<<<dim3(3, NBC), 128>>>();
        k_rowdft<<<NBC, 128>>>();
        k_mix<<<512, 256>>>(d);
        k_inv2d<<<NBC, 256>>>();
        k_mlp1<<<dim3(mlpblocks, NB), 256>>>(m1w, m1b, d);
        k_mlp2<<<dim3(mlpblocks, NB), 256>>>(m2w, m2b, wwp, wbp, d);
    }

    k_head<<<dim3(64, NB), 256>>>(q1w, q1b, q2w, q2b, out);
}

// round 13
// speedup vs baseline: 1.0518x; 1.0515x over previous
#include <cuda_runtime.h>
#include <math.h>
#include <stdint.h>

// ---------------------------------------------------------------------------
// FNO2d: B=16, Cin=5, S=128, W=64 ch, M=16 modes, D=4 layers, PAD=9 -> H=137
// Packed fp32 (fma.rn.f32x2) everywhere. coldft = round-10 proven shape.
// inv2d phase 1 reworked with packed-ky accumulators on split re/im planes.
// ---------------------------------------------------------------------------

#define NB 16
#define NC 64
#define NH 137
#define NPIX (137*137)      // 18769
#define NM 16
#define NKX 32
#define ND 4
#define NBC (NB*NC)         // 1024

typedef unsigned long long u64t;

static __device__ __align__(16) float g_x[NBC*NPIX];       // field [bc][x*137+y]
static __device__ __align__(16) float g_a[NBC*NPIX];       // scratch
static __device__ __align__(16) float g_Y[NBC*NH*32];      // col DFT [bc][x][2m+p]
static __device__ __align__(16) float g_Z[512*2*NBC];      // spectrum [kk][p][bc]
static __device__ __align__(16) float g_S[NBC*1024];       // mixed [bo][kx][ky][p]
static __device__ __align__(16) float g_wm[ND*512*2*4096]; // [d][kk][p][i*64+o]
static __device__ __align__(16) float g_Ft[NH*32];         // fwd col [y][2m+p]
static __device__ __align__(16) float g_Gt[NH*64];         // fwd row [x][2kx+p]
static __device__ __align__(16) float g_Et[32*2*NH];       // inv row [kx][2x+p]
static __device__ __align__(16) float g_Tt[NH*32];         // inv col [y][2ky+p]

__device__ __forceinline__ float gelu_f(float v) {
    return 0.5f * v * (1.0f + erff(v * 0.70710678118654752440f));
}

// ---------------- packed fp32 (f32x2) primitives ---------------------------
__device__ __forceinline__ u64t ffma2(u64t a, u64t b, u64t c) {
    u64t d;
    asm("fma.rn.f32x2 %0, %1, %2, %3;" : "=l"(d) : "l"(a), "l"(b), "l"(c));
    return d;
}
__device__ __forceinline__ u64t pack2(float lo, float hi) {
    u64t d;
    asm("mov.b64 %0, {%1, %2};" : "=l"(d) : "f"(lo), "f"(hi));
    return d;
}
__device__ __forceinline__ void unpack2(u64t v, float& lo, float& hi) {
    asm("mov.b64 {%0, %1}, %2;" : "=f"(lo), "=f"(hi) : "l"(v));
}
#define ZERO2 0ULL

// ---------------- twiddle tables (double-precision sincos) -----------------
__global__ void k_tables() {
    int idx = blockIdx.x * blockDim.x + threadIdx.x;
    if (idx >= NKX * NH) return;
    int j = idx / NH, t = idx - j * NH;
    int gk = (j < NM) ? j : (NH - NKX + j);
    const double TWO_PI = 6.283185307179586476925286766559;
    double th = TWO_PI * (double)gk * (double)t / (double)NH;
    double s, c;
    sincos(th, &s, &c);
    g_Gt[t*64 + 2*j]     = (float)c;
    g_Gt[t*64 + 2*j + 1] = (float)(-s);
    g_Et[j*(2*NH) + 2*t]     = (float)c;
    g_Et[j*(2*NH) + 2*t + 1] = (float)(s);
    if (j < NM) {
        g_Ft[t*32 + 2*j]     = (float)c;
        g_Ft[t*32 + 2*j + 1] = (float)(-s);
        double wgt = ((j == 0) ? 1.0 : 2.0) / ((double)NH * (double)NH);
        g_Tt[t*32 + 2*j]     = (float)(wgt * c);
        g_Tt[t*32 + 2*j + 1] = (float)(-wgt * s);
    }
}

// ------------- spectral weight transpose: [d][p][i][o][mx][my] -> wm -------
__global__ void k_wt(const float* __restrict__ sw1, const float* __restrict__ sw2) {
    __shared__ float tile[32][33];
    int d   = blockIdx.z >> 2;
    int p   = (blockIdx.z >> 1) & 1;
    int arr = blockIdx.z & 1;
    const float* src = (arr ? sw2 : sw1) + (size_t)(d*2 + p) * 4096 * 256;
    int mxy = blockIdx.x * 32 + threadIdx.x;
    int io  = blockIdx.y * 32 + threadIdx.y;
    tile[threadIdx.y][threadIdx.x] = src[(size_t)io * 256 + mxy];
    __syncthreads();
    int mxy2 = blockIdx.x * 32 + threadIdx.y;
    int io2  = blockIdx.y * 32 + threadIdx.x;
    g_wm[((size_t)(d*512 + arr*256 + mxy2) * 2 + p) * 4096 + io2] = tile[threadIdx.x][threadIdx.y];
}

// ---------------- embed: concat grids, project 7->64, zero-pad -------------
__global__ __launch_bounds__(160) void k_embed(const float* __restrict__ xin,
                                               const float* __restrict__ pw,
                                               const float* __restrict__ pb) {
    __shared__ float spw[448];
    __shared__ float spb[64];
    int tid = threadIdx.x;
    for (int j = tid; j < 448; j += 160) spw[j] = pw[j];
    if (tid < 64) spb[tid] = pb[tid];
    __syncthreads();
    int b = blockIdx.y, x = blockIdx.x, y = tid;
    if (y >= NH) return;
    bool interior = (x < 128 && y < 128);
    float c[5]; float gx = 0.f, gy = 0.f;
    if (interior) {
        const float* src = xin + ((size_t)(b*5) * 128 + x) * 128 + y;
        #pragma unroll
        for (int i = 0; i < 5; i++) c[i] = src[(size_t)i * 128 * 128];
        const float step = 1.0f / 127.0f;
        gx = x * step; gy = y * step;
    }
    float* dst = g_x + ((size_t)(b*64) * NH + x) * NH + y;
    #pragma unroll 4
    for (int dd = 0; dd < 64; dd++) {
        float s = 0.f;
        if (interior) {
            s = spb[dd];
            #pragma unroll
            for (int i = 0; i < 5; i++) s += c[i] * spw[i*64 + dd];
            s += gx * spw[5*64 + dd] + gy * spw[6*64 + dd];
        }
        dst[(size_t)dd * NPIX] = s;
    }
}

// ------- forward column DFT: 32-row tile, row-pair f32x2 packing -----------
__global__ __launch_bounds__(128) void k_coldft() {
    __shared__ __align__(16) float sx[NH*34];   // [y][xr] pitch 34 (even)
    int bc = blockIdx.y;
    int x0 = blockIdx.x * 32;
    int tid = threadIdx.x;
    const float* xin = g_x + (size_t)bc * NPIX;
    for (int idx = tid; idx < 32*NH; idx += 128) {
        int xr = idx / NH, y = idx - xr*NH;
        float v = (x0 + xr < NH) ? xin[(size_t)(x0+xr)*NH + y] : 0.f;
        sx[y*34 + xr] = v;
    }
    __syncthreads();
    int cg = tid & 15, rg = tid >> 4;     // 16 col-groups x 8 row-groups
    int c0 = cg*2, r0 = rg*4;             // 2 cols x 4 rows (2 pairs)
    u64t a00 = ZERO2, a01 = ZERO2, a10 = ZERO2, a11 = ZERO2;
    #pragma unroll 4
    for (int y = 0; y < NH; y++) {
        float2 f = *(const float2*)&g_Ft[y*32 + c0];   // L1-resident
        u64t fx = pack2(f.x, f.x), fy = pack2(f.y, f.y);
        const u64t* px = (const u64t*)&sx[y*34 + r0];  // even offset -> 8B ok
        u64t p0 = px[0], p1 = px[1];
        a00 = ffma2(p0, fx, a00); a01 = ffma2(p0, fy, a01);
        a10 = ffma2(p1, fx, a10); a11 = ffma2(p1, fy, a11);
    }
    int r = x0 + r0;
    float u0, u1, v0, v1;
    unpack2(a00, u0, u1); unpack2(a01, v0, v1);
    if (r < NH)     { size_t o = ((size_t)bc*NH + r    )*32 + c0; g_Y[o] = u0; g_Y[o+1] = v0; }
    if (r + 1 < NH) { size_t o = ((size_t)bc*NH + r + 1)*32 + c0; g_Y[o] = u1; g_Y[o+1] = v1; }
    unpack2(a10, u0, u1); unpack2(a11, v0, v1);
    if (r + 2 < NH) { size_t o = ((size_t)bc*NH + r + 2)*32 + c0; g_Y[o] = u0; g_Y[o+1] = v0; }
    if (r + 3 < NH) { size_t o = ((size_t)bc*NH + r + 3)*32 + c0; g_Y[o] = u1; g_Y[o+1] = v1; }
}

// ------- forward row DFT over x: C[16ky x 32kx] complex, K=137 -------------
__global__ __launch_bounds__(128) void k_rowdft() {
    __shared__ __align__(16) float ys[NH*36];   // [x][2ky+p] pad 36
    int bc = blockIdx.x;
    int tid = threadIdx.x;
    for (int idx = tid; idx < NH*32; idx += 128) {
        int x = idx >> 5, c = idx & 31;
        ys[x*36 + c] = g_Y[((size_t)bc*NH + x)*32 + c];
    }
    __syncthreads();
    int tx = tid & 31;            // kx
    int ty = tid >> 5;            // ky group of 4
    u64t acc0 = ZERO2, acc1 = ZERO2, acc2 = ZERO2, acc3 = ZERO2;  // (re,im)
    #pragma unroll 2
    for (int x = 0; x < NH; x++) {
        const float4* yp = (const float4*)&ys[x*36 + ty*8];
        float4 yA = yp[0];
        float4 yB = yp[1];
        float gc = g_Gt[x*64 + 2*tx];
        float gs = g_Gt[x*64 + 2*tx + 1];
        u64t gP = pack2(gc, gs);
        u64t gN = pack2(-gs, gc);
        acc0 = ffma2(pack2(yA.x, yA.x), gP, ffma2(pack2(yA.y, yA.y), gN, acc0));
        acc1 = ffma2(pack2(yA.z, yA.z), gP, ffma2(pack2(yA.w, yA.w), gN, acc1));
        acc2 = ffma2(pack2(yB.x, yB.x), gP, ffma2(pack2(yB.y, yB.y), gN, acc2));
        acc3 = ffma2(pack2(yB.z, yB.z), gP, ffma2(pack2(yB.w, yB.w), gN, acc3));
    }
    u64t accs[4] = {acc0, acc1, acc2, acc3};
    #pragma unroll
    for (int j = 0; j < 4; j++) {
        int ky = ty*4 + j;
        size_t base = (size_t)((tx*16 + ky)*2)*NBC + bc;
        float re, im;
        unpack2(accs[j], re, im);
        g_Z[base]       = re;
        g_Z[base + NBC] = im;
    }
}

// --- spectral channel mix: batch-pair f32x2 packing, Z transposed in smem ---
__global__ __launch_bounds__(256) void k_mix(int d) {
    __shared__ __align__(16) float zrt[64*18], zit[64*18];   // [chan][batch] pitch 18
    __shared__ float wr[4096], wi[4096];
    int kk = blockIdx.x;
    int tid = threadIdx.x;
    const float* wb = g_wm + ((size_t)(d*512 + kk) * 2) * 4096;
    for (int idx = tid; idx < 1024; idx += 256) {
        int chan = idx & 63, b = idx >> 6;
        zrt[chan*18 + b] = g_Z[(size_t)(kk*2)*NBC + idx];
        zit[chan*18 + b] = g_Z[(size_t)(kk*2 + 1)*NBC + idx];
    }
    for (int idx = tid; idx < 4096; idx += 256) {
        wr[idx] = wb[idx];
        wi[idx] = wb[4096 + idx];
    }
    __syncthreads();
    int kx = kk >> 4, ky = kk & 15;
    int o = tid & 63, bg = tid >> 6;      // 4 batches (2 pairs) per thread
    u64t accr0 = ZERO2, acci0 = ZERO2, accr1 = ZERO2, acci1 = ZERO2;
    #pragma unroll 2
    for (int i = 0; i < 64; i++) {
        float wrv = wr[i*64 + o], wiv = wi[i*64 + o];
        u64t w_r = pack2(wrv, wrv);
        u64t w_i = pack2(wiv, wiv);
        u64t w_n = pack2(-wiv, -wiv);
        const u64t* zr2 = (const u64t*)&zrt[i*18 + bg*4];   // even offsets
        const u64t* zi2 = (const u64t*)&zit[i*18 + bg*4];
        u64t a0 = zr2[0], a1 = zr2[1];
        u64t b0 = zi2[0], b1 = zi2[1];
        accr0 = ffma2(a0, w_r, ffma2(b0, w_n, accr0));
        acci0 = ffma2(a0, w_i, ffma2(b0, w_r, acci0));
        accr1 = ffma2(a1, w_r, ffma2(b1, w_n, accr1));
        acci1 = ffma2(a1, w_i, ffma2(b1, w_r, acci1));
    }
    float r0, r1, r2, r3, i0, i1, i2, i3;
    unpack2(accr0, r0, r1); unpack2(acci0, i0, i1);
    unpack2(accr1, r2, r3); unpack2(acci1, i2, i3);
    int bbase = bg*4;
    size_t tail = (size_t)kx*32 + ky*2;
    *(u64t*)&g_S[(size_t)((bbase+0)*64 + o)*1024 + tail] = pack2(r0, i0);
    *(u64t*)&g_S[(size_t)((bbase+1)*64 + o)*1024 + tail] = pack2(r1, i1);
    *(u64t*)&g_S[(size_t)((bbase+2)*64 + o)*1024 + tail] = pack2(r2, i2);
    *(u64t*)&g_S[(size_t)((bbase+3)*64 + o)*1024 + tail] = pack2(r3, i3);
}

// ------- fused inverse 2D: invrow (packed-ky) + invcol, one block per bo ----
__global__ __launch_bounds__(256) void k_inv2d() {
    __shared__ __align__(16) float ssr[512], ssi[512];   // [kx][ky] split planes
    __shared__ __align__(16) float su[NH*34];    // [x][2ky+p] pitch 34
    __shared__ __align__(16) float ts[NH*36];    // [y][2ky+p] pitch 36
    int bo = blockIdx.x, tid = threadIdx.x;
    for (int idx = tid; idx < 1024; idx += 256) {
        float v = g_S[(size_t)bo*1024 + idx];
        int kx = idx >> 5, r = idx & 31;
        if (r & 1) ssi[kx*16 + (r >> 1)] = v;
        else       ssr[kx*16 + (r >> 1)] = v;
    }
    for (int idx = tid; idx < NH*32; idx += 256) {
        int y = idx >> 5, c = idx & 31;
        ts[y*36 + c] = g_Tt[idx];
    }
    __syncthreads();
    // phase 1: inverse row transform -> su. packed-ky accumulators (4 pairs).
    for (int t = tid; t < 2*NH; t += 256) {
        int x = t >> 1;
        int ky0 = (t & 1) * 8;
        u64t aR[4], aI[4];
        #pragma unroll
        for (int j = 0; j < 4; j++) { aR[j] = ZERO2; aI[j] = ZERO2; }
        for (int k = 0; k < 32; k++) {
            float2 e = *(const float2*)&g_Et[k*(2*NH) + 2*x];    // (cos,+sin), L1
            u64t exx = pack2(e.x, e.x);
            u64t eyy = pack2(e.y, e.y);
            u64t ney = pack2(-e.y, -e.y);
            const u64t* sr2 = (const u64t*)&ssr[k*16 + ky0];     // broadcast pairs
            const u64t* si2 = (const u64t*)&ssi[k*16 + ky0];
            #pragma unroll
            for (int j = 0; j < 4; j++) {
                u64t sr = sr2[j], si = si2[j];
                aR[j] = ffma2(sr, exx, ffma2(si, ney, aR[j]));
                aI[j] = ffma2(sr, eyy, ffma2(si, exx, aI[j]));
            }
        }
        u64t* up = (u64t*)&su[x*34 + 2*ky0];
        #pragma unroll
        for (int j = 0; j < 4; j++) {
            float r0, r1, i0, i1;
            unpack2(aR[j], r0, r1);
            unpack2(aI[j], i0, i1);
            up[2*j]   = pack2(r0, i0);   // (re,im) for ky0+2j
            up[2*j+1] = pack2(r1, i1);   // (re,im) for ky0+2j+1
        }
    }
    __syncthreads();
    // phase 2: inverse column transform, lane = y, coalesced stores
    int ly = tid & 31, xg = tid >> 5;
    float* dst = g_a + (size_t)bo*NPIX;
    for (int x = xg; x < NH; x += 8) {
        u64t u2[16];
        const u64t* up = (const u64t*)&su[x*34];
        #pragma unroll
        for (int k = 0; k < 16; k++) u2[k] = up[k];   // broadcast
        for (int y = ly; y < NH; y += 32) {
            const ulonglong2* t2 = (const ulonglong2*)&ts[y*36];
            u64t acc2 = ZERO2;
            #pragma unroll
            for (int k2 = 0; k2 < 8; k2++) {
                ulonglong2 t = t2[k2];
                acc2 = ffma2(u2[2*k2], t.x, acc2);
                acc2 = ffma2(u2[2*k2+1], t.y, acc2);
            }
            float lo, hi;
            unpack2(acc2, lo, hi);
            dst[(size_t)x*NH + y] = lo + hi;
        }
    }
}

// ---------------- conv1x1 (mlp1) + exact gelu, in-place on g_a -------------
__global__ __launch_bounds__(256) void k_mlp1(const float* __restrict__ w,
                                              const float* __restrict__ bias, int d) {
    __shared__ __align__(16) float swT[4096];   // [i*64+o]
    __shared__ float sb[64];
    int tid = threadIdx.x;
    const float* wsrc = w + (size_t)d*4096;     // (o,i)
    for (int j = tid; j < 4096; j += 256) swT[j] = wsrc[(j & 63)*64 + (j >> 6)];
    if (tid < 64) sb[tid] = bias[d*64 + tid];
    __syncthreads();
    int b = blockIdx.y;
    int p = blockIdx.x*256 + tid;
    if (p >= NPIX) return;
    u64t acc2[32];
    #pragma unroll
    for (int j = 0; j < 32; j++) acc2[j] = pack2(sb[2*j], sb[2*j+1]);
    float* base = g_a + (size_t)b*64*NPIX + p;
    float a = base[0];
    for (int i = 0; i < 64; i++) {
        float an = (i < 63) ? base[(size_t)(i+1)*NPIX] : 0.0f;
        u64t av = pack2(a, a);
        const ulonglong2* w2 = (const ulonglong2*)(swT + i*64);
        #pragma unroll
        for (int q = 0; q < 16; q++) {
            ulonglong2 ww = w2[q];
            acc2[2*q]   = ffma2(ww.x, av, acc2[2*q]);
            acc2[2*q+1] = ffma2(ww.y, av, acc2[2*q+1]);
        }
        a = an;
    }
    #pragma unroll
    for (int j = 0; j < 32; j++) {
        float lo, hi;
        unpack2(acc2[j], lo, hi);
        base[(size_t)(2*j)*NPIX]   = gelu_f(lo);
        base[(size_t)(2*j+1)*NPIX] = gelu_f(hi);
    }
}

// -------- fused conv1x1 (mlp2) + skip conv (ww) + gelu, writes g_x ---------
__global__ __launch_bounds__(256) void k_mlp2(const float* __restrict__ w2p,
                                              const float* __restrict__ b2,
                                              const float* __restrict__ wwp,
                                              const float* __restrict__ wbp, int d) {
    __shared__ __align__(16) float s2[4096];
    __shared__ __align__(16) float s3[4096];
    __shared__ float sb[64];
    int tid = threadIdx.x;
    const float* w2s = w2p + (size_t)d*4096;
    const float* w3s = wwp + (size_t)d*4096;
    for (int j = tid; j < 4096; j += 256) {
        int o = j & 63, i = j >> 6;
        s2[j] = w2s[o*64 + i];
        s3[j] = w3s[o*64 + i];
    }
    if (tid < 64) sb[tid] = b2[d*64 + tid] + wbp[d*64 + tid];
    __syncthreads();
    int b = blockIdx.y;
    int p = blockIdx.x*256 + tid;
    if (p >= NPIX) return;
    u64t acc2[32];
    #pragma unroll
    for (int j = 0; j < 32; j++) acc2[j] = pack2(sb[2*j], sb[2*j+1]);
    const float* asrc = g_a + (size_t)b*64*NPIX + p;
    float* xsrc = g_x + (size_t)b*64*NPIX + p;
    float av = asrc[0], xv = xsrc[0];
    for (int i = 0; i < 64; i++) {
        float an = (i < 63) ? asrc[(size_t)(i+1)*NPIX] : 0.0f;
        float xn = (i < 63) ? xsrc[(size_t)(i+1)*NPIX] : 0.0f;
        u64t av2 = pack2(av, av);
        u64t xv2 = pack2(xv, xv);
        const ulonglong2* wa = (const ulonglong2*)(s2 + i*64);
        const ulonglong2* wb4 = (const ulonglong2*)(s3 + i*64);
        #pragma unroll
        for (int q = 0; q < 16; q++) {
            ulonglong2 wwa = wa[q];
            ulonglong2 wwb = wb4[q];
            acc2[2*q]   = ffma2(wwa.x, av2, ffma2(wwb.x, xv2, acc2[2*q]));
            acc2[2*q+1] = ffma2(wwa.y, av2, ffma2(wwb.y, xv2, acc2[2*q+1]));
        }
        av = an; xv = xn;
    }
    #pragma unroll
    for (int j = 0; j < 32; j++) {
        float lo, hi;
        unpack2(acc2[j], lo, hi);
        xsrc[(size_t)(2*j)*NPIX]   = gelu_f(lo);
        xsrc[(size_t)(2*j+1)*NPIX] = gelu_f(hi);
    }
}

// -------- head: crop + q1(64->256) + gelu + q2(256->1), two m-halves -------
__global__ __launch_bounds__(256) void k_head(const float* __restrict__ q1w,
                                              const float* __restrict__ q1b,
                                              const float* __restrict__ q2w,
                                              const float* __restrict__ q2b,
                                              float* __restrict__ out) {
    __shared__ __align__(16) float sw[8192];
    __shared__ float sb1[128], s2[128];
    int tid = threadIdx.x, b = blockIdx.y;
    int idx = blockIdx.x*256 + tid;
    int x = idx >> 7, y = idx & 127;
    const float* src = g_x + (size_t)b*64*NPIX + x*NH + y;
    u64t v2[32];
    #pragma unroll
    for (int i = 0; i < 32; i++)
        v2[i] = pack2(src[(size_t)(2*i)*NPIX], src[(size_t)(2*i+1)*NPIX]);
    float o = q2b[0];
    for (int half = 0; half < 2; half++) {
        __syncthreads();
        for (int j = tid; j < 8192; j += 256) sw[j] = q1w[half*8192 + j];
        if (tid < 128) { sb1[tid] = q1b[half*128 + tid]; s2[tid] = q2w[half*128 + tid]; }
        __syncthreads();
        for (int m = 0; m < 128; m++) {
            u64t h2a = ZERO2, h2b = ZERO2;
            const ulonglong2* w2 = (const ulonglong2*)(sw + m*64);
            #pragma unroll
            for (int q = 0; q < 16; q++) {
                ulonglong2 ww = w2[q];
                h2a = ffma2(ww.x, v2[2*q],   h2a);
                h2b = ffma2(ww.y, v2[2*q+1], h2b);
            }
            float l0, h0, l1, h1;
            unpack2(h2a, l0, h0);
            unpack2(h2b, l1, h1);
            o += s2[m] * gelu_f(sb1[m] + (l0 + h0) + (l1 + h1));
        }
    }
    out[(size_t)b*16384 + idx] = o;
}

// ---------------------------------------------------------------------------
extern "C" void kernel_launch(void* const* d_in, const int* in_sizes, int n_in,
                              void* d_out, int out_size) {
    const float* x   = (const float*)d_in[0];
    const float* p_w = (const float*)d_in[1];
    const float* p_b = (const float*)d_in[2];
    const float* sw1 = (const float*)d_in[3];
    const float* sw2 = (const float*)d_in[4];
    const float* m1w = (const float*)d_in[5];
    const float* m1b = (const float*)d_in[6];
    const float* m2w = (const float*)d_in[7];
    const float* m2b = (const float*)d_in[8];
    const float* wwp = (const float*)d_in[9];
    const float* wbp = (const float*)d_in[10];
    const float* q1w = (const float*)d_in[11];
    const float* q1b = (const float*)d_in[12];
    const float* q2w = (const float*)d_in[13];
    const float* q2b = (const float*)d_in[14];
    float* out = (float*)d_out;

    k_tables<<<18, 256>>>();
    k_wt<<<dim3(8, 128, 16), dim3(32, 32)>>>(sw1, sw2);
    k_embed<<<dim3(137, 16), 160>>>(x, p_w, p_b);

    const int mlpblocks = (NPIX + 255) / 256;
    for (int d = 0; d < ND; d++) {
        k_coldft<<<dim3(5, NBC), 128>>>();
        k_rowdft<<<NBC, 128>>>();
        k_mix<<<512, 256>>>(d);
        k_inv2d<<<NBC, 256>>>();
        k_mlp1<<<dim3(mlpblocks, NB), 256>>>(m1w, m1b, d);
        k_mlp2<<<dim3(mlpblocks, NB), 256>>>(m2w, m2b, wwp, wbp, d);
    }

    k_head<<<dim3(64, NB), 256>>>(q1w, q1b, q2w, q2b, out);
}